// round 1
// baseline (speedup 1.0000x reference)
#include <cuda_runtime.h>
#include <math.h>

#define B_   4
#define T_   2048
#define D_   1024
#define NH_  8
#define H_   128
#define M_   (B_*T_)

// Scratch (static __device__ — no allocation allowed in kernel_launch)
__device__ float g_qtmp[(size_t)M_*D_];
__device__ float g_ktmp[(size_t)M_*D_];
__device__ float g_q[(size_t)M_*D_];   // [B,N,T,H]
__device__ float g_k[(size_t)M_*D_];   // [B,N,T,H]
__device__ float g_v[(size_t)M_*D_];   // [B,N,T,H]

// ---------------------------------------------------------------------------
// GEMM: out[m][n] = sum_k A[m][k] * W[n][k]   (y = x @ W^T)
// 128x128x16 tiles, 256 threads, 8x8 microtile.
// TOUT=0: out is [M, D] row-major. TOUT=1: out scattered to [B,N,T,H].
// ---------------------------------------------------------------------------
template<int TOUT>
__global__ __launch_bounds__(256, 1)
void gemm_kernel(const float* __restrict__ A, const float* __restrict__ W,
                 float* __restrict__ out)
{
    __shared__ float As[16][132];   // [k][m], padded stride
    __shared__ float Bs[16][132];   // [k][n]
    const int t  = threadIdx.x;
    const int tx = t & 15, ty = t >> 4;
    const int m0 = blockIdx.y * 128;
    const int n0 = blockIdx.x * 128;

    float acc[8][8];
#pragma unroll
    for (int i = 0; i < 8; i++)
#pragma unroll
        for (int j = 0; j < 8; j++) acc[i][j] = 0.f;

    for (int k0 = 0; k0 < D_; k0 += 16) {
#pragma unroll
        for (int i = 0; i < 2; i++) {
            int f = t + i * 256;          // 512 float4 per tile
            int r = f >> 2;               // 0..127
            int c = (f & 3) << 2;         // 0,4,8,12
            float4 av = *(const float4*)(A + (size_t)(m0 + r) * D_ + k0 + c);
            As[c+0][r] = av.x; As[c+1][r] = av.y; As[c+2][r] = av.z; As[c+3][r] = av.w;
            float4 bv = *(const float4*)(W + (size_t)(n0 + r) * D_ + k0 + c);
            Bs[c+0][r] = bv.x; Bs[c+1][r] = bv.y; Bs[c+2][r] = bv.z; Bs[c+3][r] = bv.w;
        }
        __syncthreads();
#pragma unroll
        for (int k = 0; k < 16; k++) {
            float a[8], b[8];
            *(float4*)&a[0] = *(const float4*)&As[k][ty*8];
            *(float4*)&a[4] = *(const float4*)&As[k][ty*8+4];
            *(float4*)&b[0] = *(const float4*)&Bs[k][tx*8];
            *(float4*)&b[4] = *(const float4*)&Bs[k][tx*8+4];
#pragma unroll
            for (int i = 0; i < 8; i++)
#pragma unroll
                for (int j = 0; j < 8; j++)
                    acc[i][j] += a[i] * b[j];
        }
        __syncthreads();
    }

#pragma unroll
    for (int i = 0; i < 8; i++) {
        int m = m0 + ty*8 + i;
        if (TOUT) {
            // scatter to [B,N,T,H]; n0+tx*8..+7 stays inside one head (H=128)
            int b    = m >> 11;
            int tpos = m & (T_ - 1);
            int n    = n0 + tx*8;
            int head = n >> 7;
            int h    = n & (H_ - 1);
            float* op = out + ((((size_t)b*NH_ + head)*T_) + tpos)*H_ + h;
            *(float4*)(op)     = make_float4(acc[i][0],acc[i][1],acc[i][2],acc[i][3]);
            *(float4*)(op + 4) = make_float4(acc[i][4],acc[i][5],acc[i][6],acc[i][7]);
        } else {
            float* op = out + (size_t)m*D_ + n0 + tx*8;
            *(float4*)(op)     = make_float4(acc[i][0],acc[i][1],acc[i][2],acc[i][3]);
            *(float4*)(op + 4) = make_float4(acc[i][4],acc[i][5],acc[i][6],acc[i][7]);
        }
    }
}

// ---------------------------------------------------------------------------
// RoPE over the full D dim (matches reference: applied before head split),
// plus transpose into [B,N,T,H].
// rot(z)[d] = d < D/2 ? -z[2d+1] : z[2(d-D/2)]
// ---------------------------------------------------------------------------
__global__ __launch_bounds__(256)
void rope_kernel(const float* __restrict__ q, const float* __restrict__ k,
                 const float* __restrict__ cosb, const float* __restrict__ sinb,
                 float* __restrict__ qo, float* __restrict__ ko)
{
    int idx = blockIdx.x * blockDim.x + threadIdx.x;
    if (idx >= M_ * D_) return;
    int d   = idx & (D_ - 1);
    int row = idx >> 10;
    int tpos = row & (T_ - 1);
    int b    = row >> 11;

    float c = cosb[(size_t)tpos * D_ + d];
    float s = sinb[(size_t)tpos * D_ + d];
    size_t base = (size_t)row * D_;

    float qv = q[base + d];
    float kv = k[base + d];
    float qr, kr;
    if (d < D_/2) { qr = -q[base + 2*d + 1];          kr = -k[base + 2*d + 1]; }
    else          { qr =  q[base + 2*(d - D_/2)];     kr =  k[base + 2*(d - D_/2)]; }

    int head = d >> 7;
    int h    = d & (H_ - 1);
    size_t oidx = ((((size_t)b*NH_ + head)*T_) + tpos)*H_ + h;
    qo[oidx] = qv * c + qr * s;
    ko[oidx] = kv * c + kr * s;
}

// ---------------------------------------------------------------------------
// Causal flash attention, fp32.
// Grid: (T/64 q-tiles, B*NH). 256 threads. One CTA per SM (117 KB smem).
// Layouts in smem: Qs/Ks are [h][m] (k-major, stride 68), Vs is [n][h],
// Ps is [n][m] (stride 68) so the PV loop reads contiguous/broadcast.
// ---------------------------------------------------------------------------
__global__ __launch_bounds__(256, 1)
void attn_kernel(const float* __restrict__ Q, const float* __restrict__ K,
                 const float* __restrict__ V, float* __restrict__ out)
{
    extern __shared__ float sm[];
    float* Qs = sm;                  // [128][68]
    float* Ks = Qs + 128*68;         // [128][68]
    float* Vs = Ks + 128*68;         // [64][128]
    float* Ps = Vs + 64*128;         // [64][68]

    const int t  = threadIdx.x;
    const int tx = t & 15, ty = t >> 4;
    const int qi = blockIdx.x;
    const int bn = blockIdx.y;
    const int q0 = qi * 64;
    const float scale = 0.08838834764831845f;  // 1/sqrt(128)

    // Load Q tile (contiguous 64x128) transposed into Qs[h][m]
    const float* Qb = Q + ((size_t)bn * T_ + q0) * H_;
#pragma unroll
    for (int i = 0; i < 8; i++) {
        int f = t + i * 256;
        int r = f >> 5;             // 0..63 (query row)
        int c = (f & 31) << 2;      // h offset 0..124
        float4 v4 = *(const float4*)(Qb + r * H_ + c);
        Qs[(c+0)*68 + r] = v4.x; Qs[(c+1)*68 + r] = v4.y;
        Qs[(c+2)*68 + r] = v4.z; Qs[(c+3)*68 + r] = v4.w;
    }

    float o[4][8];
#pragma unroll
    for (int i = 0; i < 4; i++)
#pragma unroll
        for (int j = 0; j < 8; j++) o[i][j] = 0.f;
    float mi[4] = {-1e30f, -1e30f, -1e30f, -1e30f};
    float li[4] = {0.f, 0.f, 0.f, 0.f};

    for (int kt = 0; kt <= qi; kt++) {
        const int k0 = kt * 64;
        const float* Kb = K + ((size_t)bn * T_ + k0) * H_;
        const float* Vb = V + ((size_t)bn * T_ + k0) * H_;

        __syncthreads();   // prev PV reads done (also covers Qs stores on iter 0)
#pragma unroll
        for (int i = 0; i < 8; i++) {
            int f = t + i * 256;
            int r = f >> 5;
            int c = (f & 31) << 2;
            float4 kv4 = *(const float4*)(Kb + r * H_ + c);
            Ks[(c+0)*68 + r] = kv4.x; Ks[(c+1)*68 + r] = kv4.y;
            Ks[(c+2)*68 + r] = kv4.z; Ks[(c+3)*68 + r] = kv4.w;
            float4 vv4 = *(const float4*)(Vb + r * H_ + c);
            *(float4*)&Vs[r * H_ + c] = vv4;
        }
        __syncthreads();

        // S = Q K^T (this thread: rows ty*4.., cols tx*4..)
        float s[4][4];
#pragma unroll
        for (int i = 0; i < 4; i++)
#pragma unroll
            for (int j = 0; j < 4; j++) s[i][j] = 0.f;

#pragma unroll 8
        for (int kk = 0; kk < H_; kk++) {
            float a[4], b[4];
            *(float4*)a = *(const float4*)&Qs[kk*68 + ty*4];
            *(float4*)b = *(const float4*)&Ks[kk*68 + tx*4];
#pragma unroll
            for (int i = 0; i < 4; i++)
#pragma unroll
                for (int j = 0; j < 4; j++)
                    s[i][j] += a[i] * b[j];
        }

        // scale + causal mask (only diagonal tile needs it)
#pragma unroll
        for (int i = 0; i < 4; i++)
#pragma unroll
            for (int j = 0; j < 4; j++) s[i][j] *= scale;
        if (kt == qi) {
#pragma unroll
            for (int i = 0; i < 4; i++)
#pragma unroll
                for (int j = 0; j < 4; j++)
                    if (tx*4 + j > ty*4 + i) s[i][j] = -1e30f;
        }

        // online softmax per row; rows owned by the 16-lane tx-group
#pragma unroll
        for (int i = 0; i < 4; i++) {
            float rm = fmaxf(fmaxf(s[i][0], s[i][1]), fmaxf(s[i][2], s[i][3]));
            rm = fmaxf(rm, __shfl_xor_sync(0xffffffffu, rm, 1));
            rm = fmaxf(rm, __shfl_xor_sync(0xffffffffu, rm, 2));
            rm = fmaxf(rm, __shfl_xor_sync(0xffffffffu, rm, 4));
            rm = fmaxf(rm, __shfl_xor_sync(0xffffffffu, rm, 8));
            float mnew  = fmaxf(mi[i], rm);
            float alpha = __expf(mi[i] - mnew);
            float rs = 0.f;
#pragma unroll
            for (int j = 0; j < 4; j++) {
                float p = __expf(s[i][j] - mnew);
                Ps[(tx*4 + j)*68 + ty*4 + i] = p;   // transposed: Ps[n][m]
                rs += p;
            }
            rs += __shfl_xor_sync(0xffffffffu, rs, 1);
            rs += __shfl_xor_sync(0xffffffffu, rs, 2);
            rs += __shfl_xor_sync(0xffffffffu, rs, 4);
            rs += __shfl_xor_sync(0xffffffffu, rs, 8);
            li[i] = li[i] * alpha + rs;
            mi[i] = mnew;
#pragma unroll
            for (int j = 0; j < 8; j++) o[i][j] *= alpha;
        }
        __syncthreads();

        // O += P V (this thread: rows ty*4.., h cols tx*8..)
#pragma unroll 4
        for (int n = 0; n < 64; n++) {
            float p[4], v[8];
            *(float4*)p     = *(const float4*)&Ps[n*68 + ty*4];
            *(float4*)&v[0] = *(const float4*)&Vs[n*H_ + tx*8];
            *(float4*)&v[4] = *(const float4*)&Vs[n*H_ + tx*8 + 4];
#pragma unroll
            for (int i = 0; i < 4; i++)
#pragma unroll
                for (int j = 0; j < 8; j++)
                    o[i][j] += p[i] * v[j];
        }
    }

    // epilogue: normalize and write out[b, t, head*H + h]
    const int b    = bn >> 3;
    const int head = bn & 7;
#pragma unroll
    for (int i = 0; i < 4; i++) {
        float inv = 1.f / li[i];
        int tq = q0 + ty*4 + i;
        float* op = out + ((size_t)b * T_ + tq) * D_ + head * H_ + tx*8;
        *(float4*)(op)     = make_float4(o[i][0]*inv, o[i][1]*inv, o[i][2]*inv, o[i][3]*inv);
        *(float4*)(op + 4) = make_float4(o[i][4]*inv, o[i][5]*inv, o[i][6]*inv, o[i][7]*inv);
    }
}

// ---------------------------------------------------------------------------
extern "C" void kernel_launch(void* const* d_in, const int* in_sizes, int n_in,
                              void* d_out, int out_size)
{
    const float* x    = (const float*)d_in[0];
    const float* wq   = (const float*)d_in[1];
    const float* wk   = (const float*)d_in[2];
    const float* wv   = (const float*)d_in[3];
    const float* cosb = (const float*)d_in[4];
    const float* sinb = (const float*)d_in[5];
    float* out = (float*)d_out;

    float *qtmp, *ktmp, *q, *k, *v;
    cudaGetSymbolAddress((void**)&qtmp, g_qtmp);
    cudaGetSymbolAddress((void**)&ktmp, g_ktmp);
    cudaGetSymbolAddress((void**)&q,    g_q);
    cudaGetSymbolAddress((void**)&k,    g_k);
    cudaGetSymbolAddress((void**)&v,    g_v);

    dim3 gg(D_/128, M_/128);
    gemm_kernel<0><<<gg, 256>>>(x, wq, qtmp);
    gemm_kernel<0><<<gg, 256>>>(x, wk, ktmp);
    gemm_kernel<1><<<gg, 256>>>(x, wv, v);      // V straight to [B,N,T,H]

    rope_kernel<<<(M_*D_)/256, 256>>>(qtmp, ktmp, cosb, sinb, q, k);

    const int smem = (128*68 + 128*68 + 64*128 + 64*68) * (int)sizeof(float); // 119808
    cudaFuncSetAttribute((const void*)attn_kernel,
                         cudaFuncAttributeMaxDynamicSharedMemorySize, smem);
    attn_kernel<<<dim3(T_/64, B_*NH_), 256, smem>>>(q, k, v, out);
}

// round 3
// speedup vs baseline: 4.5282x; 4.5282x over previous
#include <cuda_runtime.h>
#include <cuda_fp16.h>
#include <math.h>
#include <stdint.h>

#define B_   4
#define T_   2048
#define D_   1024
#define NH_  8
#define H_   128
#define M_   (B_*T_)

// ---------------- scratch (no runtime allocation allowed) -------------------
__device__ float  g_qtmp[(size_t)M_*D_];
__device__ float  g_ktmp[(size_t)M_*D_];
__device__ float  g_q[(size_t)M_*D_];      // [B,N,T,H] tf32-rounded
__device__ float  g_k[(size_t)M_*D_];      // [B,N,T,H] tf32-rounded
__device__ __half g_vh[(size_t)M_*D_];     // [B,N,H,T] fp16 (h-major!)
__device__ float  g_xr[(size_t)M_*D_];     // x rounded to tf32-nearest
__device__ float  g_wr[(size_t)3*D_*D_];   // wq|wk|wv rounded to tf32-nearest

// ---------------- helpers ----------------------------------------------------
static __device__ __forceinline__ uint32_t smem_u32(const void* p) {
    uint32_t a;
    asm("{ .reg .u64 t; cvta.to.shared.u64 t, %1; cvt.u32.u64 %0, t; }"
        : "=r"(a) : "l"(p));
    return a;
}
static __device__ __forceinline__ void cp16(uint32_t dst, const void* src) {
    asm volatile("cp.async.cg.shared.global [%0], [%1], 16;" :: "r"(dst), "l"(src));
}
static __device__ __forceinline__ void cp_commit() {
    asm volatile("cp.async.commit_group;");
}
static __device__ __forceinline__ void cp_wait0() {
    asm volatile("cp.async.wait_group 0;" ::: "memory");
}
static __device__ __forceinline__ void cp_wait1() {
    asm volatile("cp.async.wait_group 1;" ::: "memory");
}
static __device__ __forceinline__ float tf32r(float x) {
    uint32_t u;
    asm("cvt.rna.tf32.f32 %0, %1;" : "=r"(u) : "f"(x));
    return __uint_as_float(u);
}
static __device__ __forceinline__ uint32_t fu(float x) { return __float_as_uint(x); }

static __device__ __forceinline__ void mma_tf32(float* d, const uint32_t* a,
                                                const uint32_t* b) {
    asm volatile(
        "mma.sync.aligned.m16n8k8.row.col.f32.tf32.tf32.f32 "
        "{%0,%1,%2,%3}, {%4,%5,%6,%7}, {%8,%9}, {%0,%1,%2,%3};"
        : "+f"(d[0]), "+f"(d[1]), "+f"(d[2]), "+f"(d[3])
        : "r"(a[0]), "r"(a[1]), "r"(a[2]), "r"(a[3]), "r"(b[0]), "r"(b[1]));
}
static __device__ __forceinline__ void mma_f16(float* d, const uint32_t* a,
                                               const uint32_t* b) {
    asm volatile(
        "mma.sync.aligned.m16n8k16.row.col.f32.f16.f16.f32 "
        "{%0,%1,%2,%3}, {%4,%5,%6,%7}, {%8,%9}, {%0,%1,%2,%3};"
        : "+f"(d[0]), "+f"(d[1]), "+f"(d[2]), "+f"(d[3])
        : "r"(a[0]), "r"(a[1]), "r"(a[2]), "r"(a[3]), "r"(b[0]), "r"(b[1]));
}
static __device__ __forceinline__ uint32_t pack_h2(float x, float y) {
    __half2 h = __floats2half2_rn(x, y);
    uint32_t u;
    memcpy(&u, &h, 4);
    return u;
}

// ---------------------------------------------------------------------------
// fp32 -> nearest-tf32 prep pass
// ---------------------------------------------------------------------------
__global__ __launch_bounds__(256)
void tf32_round4(const float4* __restrict__ s, float4* __restrict__ d, int n4)
{
    int i = blockIdx.x * 256 + threadIdx.x;
    if (i >= n4) return;
    float4 v = s[i];
    d[i] = make_float4(tf32r(v.x), tf32r(v.y), tf32r(v.z), tf32r(v.w));
}

// ---------------------------------------------------------------------------
// mma.sync tf32 GEMM: out[m][n] = sum_k A[m][k]*W[n][k]
// 128x128 tile, 8 warps (2m x 4n), warp 64x32, K-step 32, double-buffered.
// z=0 -> qtmp [M,D], z=1 -> ktmp [M,D], z=2 -> g_vh [B,N,H,T] fp16
// ---------------------------------------------------------------------------
#define GSTAGE 36864          // bytes per stage (A 18432 + B 18432)
#define GSMEM  (2*GSTAGE)

__global__ __launch_bounds__(256, 2)
void gemm_mma_kernel(const float* __restrict__ X, const float* __restrict__ Wall,
                     float* __restrict__ qtmp, float* __restrict__ ktmp,
                     __half* __restrict__ vh)
{
    extern __shared__ char smem[];
    const uint32_t sb = smem_u32(smem);
    const int t   = threadIdx.x;
    const int w   = t >> 5;
    const int lid = t & 31;
    const int wm  = w >> 2;           // 0..1
    const int wn  = w & 3;            // 0..3
    const int lr  = lid >> 2;         // 0..7
    const int lc  = lid & 3;          // 0..3
    const int n0  = blockIdx.x * 128;
    const int m0  = blockIdx.y * 128;
    const int z   = blockIdx.z;
    const float* W = Wall + (size_t)z * D_ * D_;

    float acc[4][4][4];
#pragma unroll
    for (int i = 0; i < 4; i++)
#pragma unroll
        for (int j = 0; j < 4; j++)
#pragma unroll
            for (int e = 0; e < 4; e++) acc[i][j][e] = 0.f;

    // ---- stage loader: A rows [m0..m0+127] x 32 floats, B rows [n0..] ----
    auto load_stage = [&](int buf, int kt) {
        const int k0 = kt * 32;
        uint32_t ab = sb + buf * GSTAGE;
        uint32_t bb = ab + 18432;
#pragma unroll
        for (int i = 0; i < 4; i++) {
            int id  = t + i * 256;          // 0..1023
            int row = id >> 3;
            int c   = id & 7;
            cp16(ab + row * 144 + c * 16, X + (size_t)(m0 + row) * D_ + k0 + c * 4);
            cp16(bb + row * 144 + c * 16, W + (size_t)(n0 + row) * D_ + k0 + c * 4);
        }
        cp_commit();
    };

    load_stage(0, 0);
    const int NK = D_ / 32;
#pragma unroll 1
    for (int kt = 0; kt < NK; kt++) {
        const int buf = kt & 1;
        if (kt + 1 < NK) load_stage(buf ^ 1, kt + 1);
        if (kt + 1 < NK) cp_wait1(); else cp_wait0();
        __syncthreads();

        const float* As  = (const float*)(smem + buf * GSTAGE);
        const float* Bs  = As + 4608;
#pragma unroll
        for (int ks = 0; ks < 4; ks++) {
            uint32_t a[4][4];
#pragma unroll
            for (int mt = 0; mt < 4; mt++) {
                int r0 = wm * 64 + mt * 16 + lr;
                int c0 = ks * 8 + lc;
                a[mt][0] = fu(As[r0 * 36 + c0]);
                a[mt][1] = fu(As[(r0 + 8) * 36 + c0]);
                a[mt][2] = fu(As[r0 * 36 + c0 + 4]);
                a[mt][3] = fu(As[(r0 + 8) * 36 + c0 + 4]);
            }
#pragma unroll
            for (int nt = 0; nt < 4; nt++) {
                int nr = wn * 32 + nt * 8 + lr;
                uint32_t b[2];
                b[0] = fu(Bs[nr * 36 + ks * 8 + lc]);
                b[1] = fu(Bs[nr * 36 + ks * 8 + lc + 4]);
#pragma unroll
                for (int mt = 0; mt < 4; mt++)
                    mma_tf32(acc[mt][nt], a[mt], b);
            }
        }
        __syncthreads();
    }

    // ---- epilogue ----
#pragma unroll
    for (int mt = 0; mt < 4; mt++) {
#pragma unroll
        for (int nt = 0; nt < 4; nt++) {
            int row = wm * 64 + mt * 16 + lr;
            int col = wn * 32 + nt * 8 + 2 * lc;
            int m   = m0 + row;
            if (z == 0) {
                *(float2*)(qtmp + (size_t)m * D_ + n0 + col) =
                    make_float2(acc[mt][nt][0], acc[mt][nt][1]);
                *(float2*)(qtmp + (size_t)(m + 8) * D_ + n0 + col) =
                    make_float2(acc[mt][nt][2], acc[mt][nt][3]);
            } else if (z == 1) {
                *(float2*)(ktmp + (size_t)m * D_ + n0 + col) =
                    make_float2(acc[mt][nt][0], acc[mt][nt][1]);
                *(float2*)(ktmp + (size_t)(m + 8) * D_ + n0 + col) =
                    make_float2(acc[mt][nt][2], acc[mt][nt][3]);
            } else {
                // V: write fp16 transposed [B,N,H,T]
                int b    = m >> 11;
                int tp   = m & (T_ - 1);
                int head = blockIdx.x;          // n0/128
                __half* vb = vh + ((size_t)(b * NH_ + head) * H_ + col) * T_ + tp;
                vb[0]            = __float2half(acc[mt][nt][0]);
                vb[T_]           = __float2half(acc[mt][nt][1]);
                vb[8]            = __float2half(acc[mt][nt][2]);
                vb[T_ + 8]       = __float2half(acc[mt][nt][3]);
            }
        }
    }
}

// ---------------------------------------------------------------------------
// RoPE (full-D) + transpose to [B,N,T,H] + tf32-nearest rounding of outputs
// ---------------------------------------------------------------------------
__global__ __launch_bounds__(256)
void rope_kernel(const float* __restrict__ q, const float* __restrict__ k,
                 const float* __restrict__ cosb, const float* __restrict__ sinb,
                 float* __restrict__ qo, float* __restrict__ ko)
{
    int idx = blockIdx.x * blockDim.x + threadIdx.x;
    if (idx >= M_ * D_) return;
    int d    = idx & (D_ - 1);
    int row  = idx >> 10;
    int tpos = row & (T_ - 1);
    int b    = row >> 11;

    float c = cosb[(size_t)tpos * D_ + d];
    float s = sinb[(size_t)tpos * D_ + d];
    size_t base = (size_t)row * D_;

    float qv = q[base + d];
    float kv = k[base + d];
    float qr, kr;
    if (d < D_/2) { qr = -q[base + 2*d + 1];      kr = -k[base + 2*d + 1]; }
    else          { qr =  q[base + 2*(d - D_/2)]; kr =  k[base + 2*(d - D_/2)]; }

    int head = d >> 7;
    int h    = d & (H_ - 1);
    size_t oidx = ((((size_t)b*NH_ + head)*T_) + tpos)*H_ + h;
    qo[oidx] = tf32r(qv * c + qr * s);
    ko[oidx] = tf32r(kv * c + kr * s);
}

// ---------------------------------------------------------------------------
// Tensor-core causal flash attention.
// Br=128, Bc=64, 8 warps x 16 rows. QK^T: tf32 mma. PV: fp16 mma, V h-major.
// smem: Qs fp32 [128][132] | Ks fp32 x2 [64][132] | Vs fp16 x2 [128][72]
// ---------------------------------------------------------------------------
#define QS_BYTES   67584
#define KS_BYTES   33792
#define VS_BYTES   18432
#define KS_OFF(b)  (QS_BYTES + (b)*KS_BYTES)
#define VS_OFF(b)  (QS_BYTES + 2*KS_BYTES + (b)*VS_BYTES)
#define ATTN_SMEM  (QS_BYTES + 2*KS_BYTES + 2*VS_BYTES)   // 172032

__global__ __launch_bounds__(256, 1)
void attn_kernel(const float* __restrict__ Q, const float* __restrict__ K,
                 const __half* __restrict__ V, float* __restrict__ out)
{
    extern __shared__ char smem[];
    const uint32_t sb = smem_u32(smem);
    const int t   = threadIdx.x;
    const int w   = t >> 5;
    const int lid = t & 31;
    const int lr  = lid >> 2;      // 0..7
    const int lc  = lid & 3;       // 0..3
    const int qi  = (gridDim.x - 1) - blockIdx.x;   // big tiles first
    const int bn  = blockIdx.y;
    const int q0  = qi * 128;
    const float scale = 0.08838834764831845f;   // 1/sqrt(128)

    const float*  Qg = Q + ((size_t)bn * T_ + q0) * H_;
    const float*  Kg = K + (size_t)bn * T_ * H_;
    const __half* Vg = V + (size_t)bn * H_ * T_;

    // ---- issue Q load + K/V tile 0 as group 0 ----
#pragma unroll
    for (int i = 0; i < 16; i++) {
        int id  = t + i * 256;         // 0..4095
        int row = id >> 5;
        int c   = id & 31;
        cp16(sb + row * 528 + c * 16, Qg + row * H_ + c * 4);
    }
    auto load_kv = [&](int kt, int buf) {
        const int k0 = kt * 64;
#pragma unroll
        for (int i = 0; i < 8; i++) {
            int id = t + i * 256;      // 0..2047
            int row = id >> 5;         // 0..63
            int c   = id & 31;
            cp16(sb + KS_OFF(buf) + row * 528 + c * 16,
                 Kg + (size_t)(k0 + row) * H_ + c * 4);
        }
#pragma unroll
        for (int i = 0; i < 4; i++) {
            int id = t + i * 256;      // 0..1023
            int row = id >> 3;         // 0..127
            int c   = id & 7;
            cp16(sb + VS_OFF(buf) + row * 144 + c * 16,
                 Vg + (size_t)row * T_ + k0 + c * 8);
        }
        cp_commit();
    };
    load_kv(0, 0);

    float o[16][4];
#pragma unroll
    for (int i = 0; i < 16; i++)
#pragma unroll
        for (int e = 0; e < 4; e++) o[i][e] = 0.f;
    float mi0 = -1e30f, mi1 = -1e30f, li0 = 0.f, li1 = 0.f;

    const int nkt = 2 * qi + 2;
#pragma unroll 1
    for (int kt = 0; kt < nkt; kt++) {
        const int buf = kt & 1;
        if (kt + 1 < nkt) load_kv(kt + 1, buf ^ 1);
        if (kt + 1 < nkt) cp_wait1(); else cp_wait0();
        __syncthreads();

        const int k0 = kt * 64;
        const bool skip = (k0 > q0 + w * 16 + 15);
        if (!skip) {
            const float*  Qs = (const float*)smem;
            const float*  Ks = (const float*)(smem + KS_OFF(buf));
            const __half* Vs = (const __half*)(smem + VS_OFF(buf));

            // ---- S = Q K^T ----
            float s[8][4];
#pragma unroll
            for (int nt = 0; nt < 8; nt++)
#pragma unroll
                for (int e = 0; e < 4; e++) s[nt][e] = 0.f;

            const int r0 = w * 16 + lr;
#pragma unroll
            for (int ks = 0; ks < 16; ks++) {
                uint32_t a[4];
                int c0 = ks * 8 + lc;
                a[0] = fu(Qs[r0 * 132 + c0]);
                a[1] = fu(Qs[(r0 + 8) * 132 + c0]);
                a[2] = fu(Qs[r0 * 132 + c0 + 4]);
                a[3] = fu(Qs[(r0 + 8) * 132 + c0 + 4]);
#pragma unroll
                for (int nt = 0; nt < 8; nt++) {
                    uint32_t b[2];
                    b[0] = fu(Ks[(nt * 8 + lr) * 132 + c0]);
                    b[1] = fu(Ks[(nt * 8 + lr) * 132 + c0 + 4]);
                    mma_tf32(s[nt], a, b);
                }
            }

#pragma unroll
            for (int nt = 0; nt < 8; nt++)
#pragma unroll
                for (int e = 0; e < 4; e++) s[nt][e] *= scale;

            // ---- causal mask (only tiles crossing the diagonal) ----
            if (k0 + 63 > q0 + w * 16) {
                const int row0g = q0 + w * 16 + lr;
#pragma unroll
                for (int nt = 0; nt < 8; nt++) {
                    int c0 = k0 + nt * 8 + 2 * lc;
                    if (c0     > row0g)     s[nt][0] = -1e30f;
                    if (c0 + 1 > row0g)     s[nt][1] = -1e30f;
                    if (c0     > row0g + 8) s[nt][2] = -1e30f;
                    if (c0 + 1 > row0g + 8) s[nt][3] = -1e30f;
                }
            }

            // ---- online softmax (rows r0, r0+8; 4 lanes share a row) ----
            float rm0 = -1e30f, rm1 = -1e30f;
#pragma unroll
            for (int nt = 0; nt < 8; nt++) {
                rm0 = fmaxf(rm0, fmaxf(s[nt][0], s[nt][1]));
                rm1 = fmaxf(rm1, fmaxf(s[nt][2], s[nt][3]));
            }
            rm0 = fmaxf(rm0, __shfl_xor_sync(0xffffffffu, rm0, 1));
            rm0 = fmaxf(rm0, __shfl_xor_sync(0xffffffffu, rm0, 2));
            rm1 = fmaxf(rm1, __shfl_xor_sync(0xffffffffu, rm1, 1));
            rm1 = fmaxf(rm1, __shfl_xor_sync(0xffffffffu, rm1, 2));

            float mn0 = fmaxf(mi0, rm0), mn1 = fmaxf(mi1, rm1);
            float al0 = __expf(mi0 - mn0), al1 = __expf(mi1 - mn1);
            float ls0 = 0.f, ls1 = 0.f;
#pragma unroll
            for (int nt = 0; nt < 8; nt++) {
                s[nt][0] = __expf(s[nt][0] - mn0);
                s[nt][1] = __expf(s[nt][1] - mn0);
                s[nt][2] = __expf(s[nt][2] - mn1);
                s[nt][3] = __expf(s[nt][3] - mn1);
                ls0 += s[nt][0] + s[nt][1];
                ls1 += s[nt][2] + s[nt][3];
            }
            ls0 += __shfl_xor_sync(0xffffffffu, ls0, 1);
            ls0 += __shfl_xor_sync(0xffffffffu, ls0, 2);
            ls1 += __shfl_xor_sync(0xffffffffu, ls1, 1);
            ls1 += __shfl_xor_sync(0xffffffffu, ls1, 2);
            li0 = li0 * al0 + ls0;  mi0 = mn0;
            li1 = li1 * al1 + ls1;  mi1 = mn1;
#pragma unroll
            for (int i = 0; i < 16; i++) {
                o[i][0] *= al0; o[i][1] *= al0;
                o[i][2] *= al1; o[i][3] *= al1;
            }

            // ---- O += P V  (P fp16 from S; V h-major in Vs) ----
#pragma unroll
            for (int kc = 0; kc < 4; kc++) {
                uint32_t pa[4];
                pa[0] = pack_h2(s[2*kc][0],   s[2*kc][1]);
                pa[1] = pack_h2(s[2*kc][2],   s[2*kc][3]);
                pa[2] = pack_h2(s[2*kc+1][0], s[2*kc+1][1]);
                pa[3] = pack_h2(s[2*kc+1][2], s[2*kc+1][3]);
#pragma unroll
                for (int nt2 = 0; nt2 < 16; nt2++) {
                    const __half* vr = Vs + (nt2 * 8 + lr) * 72 + kc * 16 + 2 * lc;
                    uint32_t b[2];
                    b[0] = *(const uint32_t*)vr;
                    b[1] = *(const uint32_t*)(vr + 8);
                    mma_f16(o[nt2], pa, b);
                }
            }
        }
        __syncthreads();
    }

    // ---- epilogue: normalize + write out[b, t, head*128 + col] ----
    const float inv0 = 1.f / li0, inv1 = 1.f / li1;
    const int b    = bn >> 3;
    const int head = bn & 7;
    const int trow = q0 + w * 16 + lr;
    float* base0 = out + ((size_t)b * T_ + trow) * D_ + head * H_ + 2 * lc;
    float* base1 = base0 + 8 * (size_t)D_;
#pragma unroll
    for (int nt2 = 0; nt2 < 16; nt2++) {
        *(float2*)(base0 + nt2 * 8) = make_float2(o[nt2][0] * inv0, o[nt2][1] * inv0);
        *(float2*)(base1 + nt2 * 8) = make_float2(o[nt2][2] * inv1, o[nt2][3] * inv1);
    }
}

// ---------------------------------------------------------------------------
extern "C" void kernel_launch(void* const* d_in, const int* in_sizes, int n_in,
                              void* d_out, int out_size)
{
    const float* x    = (const float*)d_in[0];
    const float* wq   = (const float*)d_in[1];
    const float* wk   = (const float*)d_in[2];
    const float* wv   = (const float*)d_in[3];
    const float* cosb = (const float*)d_in[4];
    const float* sinb = (const float*)d_in[5];
    float* out = (float*)d_out;

    float *qtmp, *ktmp, *q, *k, *xr, *wr;
    __half* vh;
    cudaGetSymbolAddress((void**)&qtmp, g_qtmp);
    cudaGetSymbolAddress((void**)&ktmp, g_ktmp);
    cudaGetSymbolAddress((void**)&q,    g_q);
    cudaGetSymbolAddress((void**)&k,    g_k);
    cudaGetSymbolAddress((void**)&vh,   g_vh);
    cudaGetSymbolAddress((void**)&xr,   g_xr);
    cudaGetSymbolAddress((void**)&wr,   g_wr);

    const int n4x = (M_ * D_) / 4;
    const int n4w = (D_ * D_) / 4;
    tf32_round4<<<(n4x + 255)/256, 256>>>((const float4*)x,  (float4*)xr, n4x);
    tf32_round4<<<(n4w + 255)/256, 256>>>((const float4*)wq, (float4*)(wr + 0*(size_t)D_*D_), n4w);
    tf32_round4<<<(n4w + 255)/256, 256>>>((const float4*)wk, (float4*)(wr + 1*(size_t)D_*D_), n4w);
    tf32_round4<<<(n4w + 255)/256, 256>>>((const float4*)wv, (float4*)(wr + 2*(size_t)D_*D_), n4w);

    cudaFuncSetAttribute((const void*)gemm_mma_kernel,
                         cudaFuncAttributeMaxDynamicSharedMemorySize, GSMEM);
    gemm_mma_kernel<<<dim3(D_/128, M_/128, 3), 256, GSMEM>>>(xr, wr, qtmp, ktmp, vh);

    rope_kernel<<<(M_*D_)/256, 256>>>(qtmp, ktmp, cosb, sinb, q, k);

    cudaFuncSetAttribute((const void*)attn_kernel,
                         cudaFuncAttributeMaxDynamicSharedMemorySize, ATTN_SMEM);
    attn_kernel<<<dim3(T_/128, B_*NH_), 256, ATTN_SMEM>>>(q, k, vh, out);
}

// round 4
// speedup vs baseline: 7.4272x; 1.6402x over previous
#include <cuda_runtime.h>
#include <cuda_fp16.h>
#include <math.h>
#include <stdint.h>

#define B_   4
#define T_   2048
#define D_   1024
#define NH_  8
#define H_   128
#define M_   (B_*T_)

// ---------------- scratch ----------------------------------------------------
__device__ float  g_qtmp[(size_t)M_*D_];
__device__ float  g_ktmp[(size_t)M_*D_];
__device__ __half g_qh[(size_t)M_*D_];     // [B,N,T,H] fp16
__device__ __half g_kh[(size_t)M_*D_];     // [B,N,T,H] fp16
__device__ __half g_vh[(size_t)M_*D_];     // [B,N,H,T] fp16 (h-major)
__device__ __half g_xh[(size_t)M_*D_];     // x fp16
__device__ __half g_wh[(size_t)3*D_*D_];   // wq|wk|wv fp16

// ---------------- helpers ----------------------------------------------------
static __device__ __forceinline__ uint32_t smem_u32(const void* p) {
    uint32_t a;
    asm("{ .reg .u64 t; cvta.to.shared.u64 t, %1; cvt.u32.u64 %0, t; }"
        : "=r"(a) : "l"(p));
    return a;
}
static __device__ __forceinline__ void cp16(uint32_t dst, const void* src) {
    asm volatile("cp.async.cg.shared.global [%0], [%1], 16;" :: "r"(dst), "l"(src));
}
static __device__ __forceinline__ void cp_commit() {
    asm volatile("cp.async.commit_group;");
}
static __device__ __forceinline__ void cp_wait0() {
    asm volatile("cp.async.wait_group 0;" ::: "memory");
}
static __device__ __forceinline__ void cp_wait1() {
    asm volatile("cp.async.wait_group 1;" ::: "memory");
}
static __device__ __forceinline__ void mma_f16(float* d, const uint32_t* a,
                                               const uint32_t* b) {
    asm volatile(
        "mma.sync.aligned.m16n8k16.row.col.f32.f16.f16.f32 "
        "{%0,%1,%2,%3}, {%4,%5,%6,%7}, {%8,%9}, {%0,%1,%2,%3};"
        : "+f"(d[0]), "+f"(d[1]), "+f"(d[2]), "+f"(d[3])
        : "r"(a[0]), "r"(a[1]), "r"(a[2]), "r"(a[3]), "r"(b[0]), "r"(b[1]));
}
static __device__ __forceinline__ void ldm_x4(uint32_t* r, uint32_t addr) {
    asm volatile("ldmatrix.sync.aligned.m8n8.x4.shared.b16 {%0,%1,%2,%3}, [%4];"
        : "=r"(r[0]), "=r"(r[1]), "=r"(r[2]), "=r"(r[3]) : "r"(addr));
}
static __device__ __forceinline__ uint32_t pack_h2(float x, float y) {
    __half2 h = __floats2half2_rn(x, y);
    uint32_t u;
    memcpy(&u, &h, 4);
    return u;
}

// ---------------------------------------------------------------------------
// fp32 -> fp16 prep
// ---------------------------------------------------------------------------
__global__ __launch_bounds__(256)
void f2h4(const float4* __restrict__ s, uint2* __restrict__ d, int n4)
{
    int i = blockIdx.x * 256 + threadIdx.x;
    if (i >= n4) return;
    float4 v = s[i];
    d[i] = make_uint2(pack_h2(v.x, v.y), pack_h2(v.z, v.w));
}

// ---------------------------------------------------------------------------
// fp16 mma GEMM: out[m][n] = sum_k A[m][k]*W[n][k], fp32 accum.
// 128x128 tile, 8 warps (2m x 4n), warp 64x32, K-chunk 64 (4x k16),
// ldmatrix fragments, double-buffered cp.async.
// z=0 -> qtmp fp32 [M,D], z=1 -> ktmp fp32 [M,D], z=2 -> g_vh fp16 [B,N,H,T]
// ---------------------------------------------------------------------------
#define GSTAGE 36864          // A 128x144B + B 128x144B
#define GSMEM  (2*GSTAGE)

__global__ __launch_bounds__(256, 2)
void gemm_mma_kernel(const __half* __restrict__ X, const __half* __restrict__ Wall,
                     float* __restrict__ qtmp, float* __restrict__ ktmp,
                     __half* __restrict__ vh)
{
    extern __shared__ char smem[];
    const uint32_t sb = smem_u32(smem);
    const int t   = threadIdx.x;
    const int w   = t >> 5;
    const int lid = t & 31;
    const int wm  = w >> 2;
    const int wn  = w & 3;
    const int lr  = lid >> 2;
    const int lc  = lid & 3;
    const int n0  = blockIdx.x * 128;
    const int m0  = blockIdx.y * 128;
    const int z   = blockIdx.z;
    const __half* W = Wall + (size_t)z * D_ * D_;

    // ldmatrix lane-address components
    const int l7  = lid & 7;
    const int lm1 = (lid >> 3) & 1;   // m & 1
    const int lm2 = lid >> 4;         // m >> 1

    float acc[4][4][4];
#pragma unroll
    for (int i = 0; i < 4; i++)
#pragma unroll
        for (int j = 0; j < 4; j++)
#pragma unroll
            for (int e = 0; e < 4; e++) acc[i][j][e] = 0.f;

    auto load_stage = [&](int buf, int kt) {
        const int k0 = kt * 64;
        uint32_t ab = sb + buf * GSTAGE;
        uint32_t bb = ab + 18432;
#pragma unroll
        for (int i = 0; i < 4; i++) {
            int id  = t + i * 256;          // 0..1023
            int row = id >> 3;
            int c   = id & 7;
            cp16(ab + row * 144 + c * 16, X + (size_t)(m0 + row) * D_ + k0 + c * 8);
            cp16(bb + row * 144 + c * 16, W + (size_t)(n0 + row) * D_ + k0 + c * 8);
        }
        cp_commit();
    };

    load_stage(0, 0);
    const int NK = D_ / 64;
#pragma unroll 1
    for (int kt = 0; kt < NK; kt++) {
        const int buf = kt & 1;
        if (kt + 1 < NK) load_stage(buf ^ 1, kt + 1);
        if (kt + 1 < NK) cp_wait1(); else cp_wait0();
        __syncthreads();

        const uint32_t As = sb + buf * GSTAGE;
        const uint32_t Bs = As + 18432;
#pragma unroll
        for (int ks = 0; ks < 4; ks++) {
            uint32_t a[4][4];
#pragma unroll
            for (int mt = 0; mt < 4; mt++) {
                int row = wm * 64 + mt * 16 + l7 + lm1 * 8;
                int kh  = ks * 16 + lm2 * 8;
                ldm_x4(a[mt], As + row * 144 + kh * 2);
            }
#pragma unroll
            for (int ntp = 0; ntp < 2; ntp++) {
                uint32_t b[4];
                int nr = wn * 32 + ntp * 16 + l7 + lm2 * 8;
                int kh = ks * 16 + lm1 * 8;
                ldm_x4(b, Bs + nr * 144 + kh * 2);
#pragma unroll
                for (int mt = 0; mt < 4; mt++) {
                    mma_f16(acc[mt][2*ntp],   a[mt], b);
                    mma_f16(acc[mt][2*ntp+1], a[mt], b + 2);
                }
            }
        }
        __syncthreads();
    }

    // ---- epilogue ----
#pragma unroll
    for (int mt = 0; mt < 4; mt++) {
#pragma unroll
        for (int nt = 0; nt < 4; nt++) {
            int row = wm * 64 + mt * 16 + lr;
            int col = wn * 32 + nt * 8 + 2 * lc;
            int m   = m0 + row;
            if (z == 0) {
                *(float2*)(qtmp + (size_t)m * D_ + n0 + col) =
                    make_float2(acc[mt][nt][0], acc[mt][nt][1]);
                *(float2*)(qtmp + (size_t)(m + 8) * D_ + n0 + col) =
                    make_float2(acc[mt][nt][2], acc[mt][nt][3]);
            } else if (z == 1) {
                *(float2*)(ktmp + (size_t)m * D_ + n0 + col) =
                    make_float2(acc[mt][nt][0], acc[mt][nt][1]);
                *(float2*)(ktmp + (size_t)(m + 8) * D_ + n0 + col) =
                    make_float2(acc[mt][nt][2], acc[mt][nt][3]);
            } else {
                int b    = m >> 11;
                int tp   = m & (T_ - 1);
                int head = blockIdx.x;
                __half* vb = vh + ((size_t)(b * NH_ + head) * H_ + col) * T_ + tp;
                vb[0]      = __float2half(acc[mt][nt][0]);
                vb[T_]     = __float2half(acc[mt][nt][1]);
                vb[8]      = __float2half(acc[mt][nt][2]);
                vb[T_ + 8] = __float2half(acc[mt][nt][3]);
            }
        }
    }
}

// ---------------------------------------------------------------------------
// RoPE (full-D) + transpose to [B,N,T,H], output fp16
// ---------------------------------------------------------------------------
__global__ __launch_bounds__(256)
void rope_kernel(const float* __restrict__ q, const float* __restrict__ k,
                 const float* __restrict__ cosb, const float* __restrict__ sinb,
                 __half* __restrict__ qo, __half* __restrict__ ko)
{
    int idx = blockIdx.x * blockDim.x + threadIdx.x;
    if (idx >= M_ * D_) return;
    int d    = idx & (D_ - 1);
    int row  = idx >> 10;
    int tpos = row & (T_ - 1);
    int b    = row >> 11;

    float c = cosb[(size_t)tpos * D_ + d];
    float s = sinb[(size_t)tpos * D_ + d];
    size_t base = (size_t)row * D_;

    float qv = q[base + d];
    float kv = k[base + d];
    float qr, kr;
    if (d < D_/2) { qr = -q[base + 2*d + 1];      kr = -k[base + 2*d + 1]; }
    else          { qr =  q[base + 2*(d - D_/2)]; kr =  k[base + 2*(d - D_/2)]; }

    int head = d >> 7;
    int h    = d & (H_ - 1);
    size_t oidx = ((((size_t)b*NH_ + head)*T_) + tpos)*H_ + h;
    qo[oidx] = __float2half(qv * c + qr * s);
    ko[oidx] = __float2half(kv * c + kr * s);
}

// ---------------------------------------------------------------------------
// fp16 tensor-core causal flash attention. Br=128, Bc=64, 8 warps x 16 rows.
// Q/K/V all fp16 in smem; ldmatrix fragments; fp32 accumulators + softmax.
// smem: Qs [128][136]h | Ks x2 [64][136]h | Vs x2 [128][72]h
// ---------------------------------------------------------------------------
#define QS_BYTES   34816
#define KS_BYTES   17408
#define VS_BYTES   18432
#define KS_OFF(b)  (QS_BYTES + (b)*KS_BYTES)
#define VS_OFF(b)  (QS_BYTES + 2*KS_BYTES + (b)*VS_BYTES)
#define ATTN_SMEM  (QS_BYTES + 2*KS_BYTES + 2*VS_BYTES)   // 106496

__global__ __launch_bounds__(256, 1)
void attn_kernel(const __half* __restrict__ Q, const __half* __restrict__ K,
                 const __half* __restrict__ V, float* __restrict__ out)
{
    extern __shared__ char smem[];
    const uint32_t sb = smem_u32(smem);
    const int t   = threadIdx.x;
    const int w   = t >> 5;
    const int lid = t & 31;
    const int lr  = lid >> 2;
    const int lc  = lid & 3;
    const int l7  = lid & 7;
    const int lm1 = (lid >> 3) & 1;
    const int lm2 = lid >> 4;
    const int qi  = (gridDim.x - 1) - blockIdx.x;
    const int bn  = blockIdx.y;
    const int q0  = qi * 128;
    const float scale = 0.08838834764831845f;

    const __half* Qg = Q + ((size_t)bn * T_ + q0) * H_;
    const __half* Kg = K + (size_t)bn * T_ * H_;
    const __half* Vg = V + (size_t)bn * H_ * T_;

#pragma unroll
    for (int i = 0; i < 8; i++) {
        int id  = t + i * 256;         // 0..2047
        int row = id >> 4;
        int c   = id & 15;
        cp16(sb + row * 272 + c * 16, Qg + row * H_ + c * 8);
    }
    auto load_kv = [&](int kt, int buf) {
        const int k0 = kt * 64;
#pragma unroll
        for (int i = 0; i < 4; i++) {
            int id  = t + i * 256;     // 0..1023
            int row = id >> 4;         // 0..63
            int c   = id & 15;
            cp16(sb + KS_OFF(buf) + row * 272 + c * 16,
                 Kg + (size_t)(k0 + row) * H_ + c * 8);
        }
#pragma unroll
        for (int i = 0; i < 4; i++) {
            int id  = t + i * 256;     // 0..1023
            int row = id >> 3;         // 0..127
            int c   = id & 7;
            cp16(sb + VS_OFF(buf) + row * 144 + c * 16,
                 Vg + (size_t)row * T_ + k0 + c * 8);
        }
        cp_commit();
    };
    load_kv(0, 0);

    float o[16][4];
#pragma unroll
    for (int i = 0; i < 16; i++)
#pragma unroll
        for (int e = 0; e < 4; e++) o[i][e] = 0.f;
    float mi0 = -1e30f, mi1 = -1e30f, li0 = 0.f, li1 = 0.f;

    const int nkt = 2 * qi + 2;
#pragma unroll 1
    for (int kt = 0; kt < nkt; kt++) {
        const int buf = kt & 1;
        if (kt + 1 < nkt) load_kv(kt + 1, buf ^ 1);
        if (kt + 1 < nkt) cp_wait1(); else cp_wait0();
        __syncthreads();

        const int k0 = kt * 64;
        if (k0 <= q0 + w * 16 + 15) {
            const uint32_t Qs  = sb;
            const uint32_t Ksb = sb + KS_OFF(buf);
            const uint32_t Vsb = sb + VS_OFF(buf);

            // ---- S = Q K^T (fp16 mma, ldmatrix frags) ----
            float s[8][4];
#pragma unroll
            for (int nt = 0; nt < 8; nt++)
#pragma unroll
                for (int e = 0; e < 4; e++) s[nt][e] = 0.f;

#pragma unroll
            for (int ks = 0; ks < 8; ks++) {
                uint32_t a[4];
                {
                    int row = w * 16 + l7 + lm1 * 8;
                    int kh  = ks * 16 + lm2 * 8;
                    ldm_x4(a, Qs + row * 272 + kh * 2);
                }
#pragma unroll
                for (int ntp = 0; ntp < 4; ntp++) {
                    uint32_t b[4];
                    int nr = ntp * 16 + l7 + lm2 * 8;
                    int kh = ks * 16 + lm1 * 8;
                    ldm_x4(b, Ksb + nr * 272 + kh * 2);
                    mma_f16(s[2*ntp],   a, b);
                    mma_f16(s[2*ntp+1], a, b + 2);
                }
            }

#pragma unroll
            for (int nt = 0; nt < 8; nt++)
#pragma unroll
                for (int e = 0; e < 4; e++) s[nt][e] *= scale;

            // ---- causal mask ----
            if (k0 + 63 > q0 + w * 16) {
                const int row0g = q0 + w * 16 + lr;
#pragma unroll
                for (int nt = 0; nt < 8; nt++) {
                    int c0 = k0 + nt * 8 + 2 * lc;
                    if (c0     > row0g)     s[nt][0] = -1e30f;
                    if (c0 + 1 > row0g)     s[nt][1] = -1e30f;
                    if (c0     > row0g + 8) s[nt][2] = -1e30f;
                    if (c0 + 1 > row0g + 8) s[nt][3] = -1e30f;
                }
            }

            // ---- online softmax ----
            float rm0 = -1e30f, rm1 = -1e30f;
#pragma unroll
            for (int nt = 0; nt < 8; nt++) {
                rm0 = fmaxf(rm0, fmaxf(s[nt][0], s[nt][1]));
                rm1 = fmaxf(rm1, fmaxf(s[nt][2], s[nt][3]));
            }
            rm0 = fmaxf(rm0, __shfl_xor_sync(0xffffffffu, rm0, 1));
            rm0 = fmaxf(rm0, __shfl_xor_sync(0xffffffffu, rm0, 2));
            rm1 = fmaxf(rm1, __shfl_xor_sync(0xffffffffu, rm1, 1));
            rm1 = fmaxf(rm1, __shfl_xor_sync(0xffffffffu, rm1, 2));

            float mn0 = fmaxf(mi0, rm0), mn1 = fmaxf(mi1, rm1);
            float al0 = __expf(mi0 - mn0), al1 = __expf(mi1 - mn1);
            float ls0 = 0.f, ls1 = 0.f;
#pragma unroll
            for (int nt = 0; nt < 8; nt++) {
                s[nt][0] = __expf(s[nt][0] - mn0);
                s[nt][1] = __expf(s[nt][1] - mn0);
                s[nt][2] = __expf(s[nt][2] - mn1);
                s[nt][3] = __expf(s[nt][3] - mn1);
                ls0 += s[nt][0] + s[nt][1];
                ls1 += s[nt][2] + s[nt][3];
            }
            ls0 += __shfl_xor_sync(0xffffffffu, ls0, 1);
            ls0 += __shfl_xor_sync(0xffffffffu, ls0, 2);
            ls1 += __shfl_xor_sync(0xffffffffu, ls1, 1);
            ls1 += __shfl_xor_sync(0xffffffffu, ls1, 2);
            li0 = li0 * al0 + ls0;  mi0 = mn0;
            li1 = li1 * al1 + ls1;  mi1 = mn1;
#pragma unroll
            for (int i = 0; i < 16; i++) {
                o[i][0] *= al0; o[i][1] *= al0;
                o[i][2] *= al1; o[i][3] *= al1;
            }

            // ---- O += P V ----
#pragma unroll
            for (int kc = 0; kc < 4; kc++) {
                uint32_t pa[4];
                pa[0] = pack_h2(s[2*kc][0],   s[2*kc][1]);
                pa[1] = pack_h2(s[2*kc][2],   s[2*kc][3]);
                pa[2] = pack_h2(s[2*kc+1][0], s[2*kc+1][1]);
                pa[3] = pack_h2(s[2*kc+1][2], s[2*kc+1][3]);
#pragma unroll
                for (int ntp = 0; ntp < 8; ntp++) {
                    uint32_t b[4];
                    int hr = ntp * 16 + l7 + lm2 * 8;
                    int th = kc * 16 + lm1 * 8;
                    ldm_x4(b, Vsb + hr * 144 + th * 2);
                    mma_f16(o[2*ntp],   pa, b);
                    mma_f16(o[2*ntp+1], pa, b + 2);
                }
            }
        }
        __syncthreads();
    }

    // ---- epilogue ----
    const float inv0 = 1.f / li0, inv1 = 1.f / li1;
    const int b    = bn >> 3;
    const int head = bn & 7;
    const int trow = q0 + w * 16 + lr;
    float* base0 = out + ((size_t)b * T_ + trow) * D_ + head * H_ + 2 * lc;
    float* base1 = base0 + 8 * (size_t)D_;
#pragma unroll
    for (int nt2 = 0; nt2 < 16; nt2++) {
        *(float2*)(base0 + nt2 * 8) = make_float2(o[nt2][0] * inv0, o[nt2][1] * inv0);
        *(float2*)(base1 + nt2 * 8) = make_float2(o[nt2][2] * inv1, o[nt2][3] * inv1);
    }
}

// ---------------------------------------------------------------------------
extern "C" void kernel_launch(void* const* d_in, const int* in_sizes, int n_in,
                              void* d_out, int out_size)
{
    const float* x    = (const float*)d_in[0];
    const float* wq   = (const float*)d_in[1];
    const float* wk   = (const float*)d_in[2];
    const float* wv   = (const float*)d_in[3];
    const float* cosb = (const float*)d_in[4];
    const float* sinb = (const float*)d_in[5];
    float* out = (float*)d_out;

    float *qtmp, *ktmp;
    __half *qh, *kh, *vh, *xh, *wh;
    cudaGetSymbolAddress((void**)&qtmp, g_qtmp);
    cudaGetSymbolAddress((void**)&ktmp, g_ktmp);
    cudaGetSymbolAddress((void**)&qh,   g_qh);
    cudaGetSymbolAddress((void**)&kh,   g_kh);
    cudaGetSymbolAddress((void**)&vh,   g_vh);
    cudaGetSymbolAddress((void**)&xh,   g_xh);
    cudaGetSymbolAddress((void**)&wh,   g_wh);

    const int n4x = (M_ * D_) / 4;
    const int n4w = (D_ * D_) / 4;
    f2h4<<<(n4x + 255)/256, 256>>>((const float4*)x,  (uint2*)xh, n4x);
    f2h4<<<(n4w + 255)/256, 256>>>((const float4*)wq, (uint2*)(wh + 0*(size_t)D_*D_), n4w);
    f2h4<<<(n4w + 255)/256, 256>>>((const float4*)wk, (uint2*)(wh + 1*(size_t)D_*D_), n4w);
    f2h4<<<(n4w + 255)/256, 256>>>((const float4*)wv, (uint2*)(wh + 2*(size_t)D_*D_), n4w);

    cudaFuncSetAttribute((const void*)gemm_mma_kernel,
                         cudaFuncAttributeMaxDynamicSharedMemorySize, GSMEM);
    gemm_mma_kernel<<<dim3(D_/128, M_/128, 3), 256, GSMEM>>>(xh, wh, qtmp, ktmp, vh);

    rope_kernel<<<(M_*D_)/256, 256>>>(qtmp, ktmp, cosb, sinb, qh, kh);

    cudaFuncSetAttribute((const void*)attn_kernel,
                         cudaFuncAttributeMaxDynamicSharedMemorySize, ATTN_SMEM);
    attn_kernel<<<dim3(T_/128, B_*NH_), 256, ATTN_SMEM>>>(qh, kh, vh, out);
}

// round 6
// speedup vs baseline: 7.9403x; 1.0691x over previous
#include <cuda_runtime.h>
#include <cuda_fp16.h>
#include <math.h>
#include <stdint.h>

#define B_   4
#define T_   2048
#define D_   1024
#define NH_  8
#define H_   128
#define M_   (B_*T_)

// ---------------- scratch ----------------------------------------------------
__device__ __half g_qth[(size_t)M_*D_];    // q pre-rope fp16 [M,D]
__device__ __half g_kth[(size_t)M_*D_];    // k pre-rope fp16 [M,D]
__device__ __half g_qh[(size_t)M_*D_];     // [B,N,T,H] fp16
__device__ __half g_kh[(size_t)M_*D_];     // [B,N,T,H] fp16
__device__ __half g_vh[(size_t)M_*D_];     // [B,N,H,T] fp16 (h-major)
__device__ __half g_xh[(size_t)M_*D_];     // x fp16
__device__ __half g_wh[(size_t)3*D_*D_];   // wq|wk|wv fp16

// ---------------- helpers ----------------------------------------------------
static __device__ __forceinline__ uint32_t smem_u32(const void* p) {
    uint32_t a;
    asm("{ .reg .u64 t; cvta.to.shared.u64 t, %1; cvt.u32.u64 %0, t; }"
        : "=r"(a) : "l"(p));
    return a;
}
static __device__ __forceinline__ void cp16(uint32_t dst, const void* src) {
    asm volatile("cp.async.cg.shared.global [%0], [%1], 16;" :: "r"(dst), "l"(src));
}
static __device__ __forceinline__ void cp_commit() {
    asm volatile("cp.async.commit_group;");
}
static __device__ __forceinline__ void cp_wait0() {
    asm volatile("cp.async.wait_group 0;" ::: "memory");
}
static __device__ __forceinline__ void cp_wait1() {
    asm volatile("cp.async.wait_group 1;" ::: "memory");
}
static __device__ __forceinline__ void mma_f16(float* d, const uint32_t* a,
                                               const uint32_t* b) {
    asm volatile(
        "mma.sync.aligned.m16n8k16.row.col.f32.f16.f16.f32 "
        "{%0,%1,%2,%3}, {%4,%5,%6,%7}, {%8,%9}, {%0,%1,%2,%3};"
        : "+f"(d[0]), "+f"(d[1]), "+f"(d[2]), "+f"(d[3])
        : "r"(a[0]), "r"(a[1]), "r"(a[2]), "r"(a[3]), "r"(b[0]), "r"(b[1]));
}
static __device__ __forceinline__ void ldm_x4(uint32_t* r, uint32_t addr) {
    asm volatile("ldmatrix.sync.aligned.m8n8.x4.shared.b16 {%0,%1,%2,%3}, [%4];"
        : "=r"(r[0]), "=r"(r[1]), "=r"(r[2]), "=r"(r[3]) : "r"(addr));
}
static __device__ __forceinline__ uint32_t pack_h2(float x, float y) {
    __half2 h = __floats2half2_rn(x, y);
    uint32_t u;
    memcpy(&u, &h, 4);
    return u;
}
static __device__ __forceinline__ float ex2(float x) {
    float r;
    asm("ex2.approx.f32 %0, %1;" : "=f"(r) : "f"(x));
    return r;
}

// ---------------------------------------------------------------------------
// Fused fp32->fp16 prep: x then wq|wk|wv (single launch)
// ---------------------------------------------------------------------------
__global__ __launch_bounds__(256)
void prep_h(const float4* __restrict__ x,  const float4* __restrict__ wq,
            const float4* __restrict__ wk, const float4* __restrict__ wv,
            uint2* __restrict__ xh, uint2* __restrict__ wh, int n4x, int n4w)
{
    int i = blockIdx.x * 256 + threadIdx.x;
    const float4* src;
    uint2* dst;
    int off;
    if (i < n4x) { src = x; dst = xh; off = i; }
    else {
        int j = i - n4x;
        int z = j / n4w;
        off = j - z * n4w;
        src = (z == 0) ? wq : (z == 1) ? wk : wv;
        dst = wh + (size_t)z * n4w;
    }
    float4 v = src[off];
    dst[off] = make_uint2(pack_h2(v.x, v.y), pack_h2(v.z, v.w));
}

// ---------------------------------------------------------------------------
// fp16 mma GEMM, 3-stage cp.async pipeline, one barrier per K-chunk.
// 128x128 tile, 8 warps (2m x 4n), K-chunk 64.
// z=0 -> qth fp16 [M,D], z=1 -> kth fp16 [M,D], z=2 -> g_vh fp16 [B,N,H,T]
// ---------------------------------------------------------------------------
#define GSTAGE 36864          // A 128x144B + B 128x144B
#define GSMEM  (3*GSTAGE)     // 110592

__global__ __launch_bounds__(256, 2)
void gemm_mma_kernel(const __half* __restrict__ X, const __half* __restrict__ Wall,
                     __half* __restrict__ qth, __half* __restrict__ kth,
                     __half* __restrict__ vh)
{
    extern __shared__ char smem[];
    const uint32_t sb = smem_u32(smem);
    const int t   = threadIdx.x;
    const int w   = t >> 5;
    const int lid = t & 31;
    const int wm  = w >> 2;
    const int wn  = w & 3;
    const int lr  = lid >> 2;
    const int lc  = lid & 3;
    const int n0  = blockIdx.x * 128;
    const int m0  = blockIdx.y * 128;
    const int z   = blockIdx.z;
    const __half* W = Wall + (size_t)z * D_ * D_;

    const int l7  = lid & 7;
    const int lm1 = (lid >> 3) & 1;
    const int lm2 = lid >> 4;

    float acc[4][4][4];
#pragma unroll
    for (int i = 0; i < 4; i++)
#pragma unroll
        for (int j = 0; j < 4; j++)
#pragma unroll
            for (int e = 0; e < 4; e++) acc[i][j][e] = 0.f;

    auto load_stage = [&](int stg, int kt) {
        const int k0 = kt * 64;
        uint32_t ab = sb + stg * GSTAGE;
        uint32_t bb = ab + 18432;
#pragma unroll
        for (int i = 0; i < 4; i++) {
            int id  = t + i * 256;
            int row = id >> 3;
            int c   = id & 7;
            cp16(ab + row * 144 + c * 16, X + (size_t)(m0 + row) * D_ + k0 + c * 8);
            cp16(bb + row * 144 + c * 16, W + (size_t)(n0 + row) * D_ + k0 + c * 8);
        }
        cp_commit();
    };

    const int NK = D_ / 64;
    load_stage(0, 0);
    load_stage(1, 1);

#pragma unroll 1
    for (int kt = 0; kt < NK; kt++) {
        if (kt == NK - 1) cp_wait0(); else cp_wait1();
        __syncthreads();
        if (kt + 2 < NK) load_stage((kt + 2) % 3, kt + 2);

        const uint32_t As = sb + (kt % 3) * GSTAGE;
        const uint32_t Bs = As + 18432;
#pragma unroll
        for (int ks = 0; ks < 4; ks++) {
            uint32_t a[4][4];
#pragma unroll
            for (int mt = 0; mt < 4; mt++) {
                int row = wm * 64 + mt * 16 + l7 + lm1 * 8;
                int kh  = ks * 16 + lm2 * 8;
                ldm_x4(a[mt], As + row * 144 + kh * 2);
            }
#pragma unroll
            for (int ntp = 0; ntp < 2; ntp++) {
                uint32_t b[4];
                int nr = wn * 32 + ntp * 16 + l7 + lm2 * 8;
                int kh = ks * 16 + lm1 * 8;
                ldm_x4(b, Bs + nr * 144 + kh * 2);
#pragma unroll
                for (int mt = 0; mt < 4; mt++) {
                    mma_f16(acc[mt][2*ntp],   a[mt], b);
                    mma_f16(acc[mt][2*ntp+1], a[mt], b + 2);
                }
            }
        }
    }

    // ---- epilogue (fp16 everywhere) ----
#pragma unroll
    for (int mt = 0; mt < 4; mt++) {
#pragma unroll
        for (int nt = 0; nt < 4; nt++) {
            int row = wm * 64 + mt * 16 + lr;
            int col = wn * 32 + nt * 8 + 2 * lc;
            int m   = m0 + row;
            uint32_t p0 = pack_h2(acc[mt][nt][0], acc[mt][nt][1]);
            uint32_t p1 = pack_h2(acc[mt][nt][2], acc[mt][nt][3]);
            if (z == 0) {
                *(uint32_t*)(qth + (size_t)m * D_ + n0 + col)       = p0;
                *(uint32_t*)(qth + (size_t)(m + 8) * D_ + n0 + col) = p1;
            } else if (z == 1) {
                *(uint32_t*)(kth + (size_t)m * D_ + n0 + col)       = p0;
                *(uint32_t*)(kth + (size_t)(m + 8) * D_ + n0 + col) = p1;
            } else {
                int b    = m >> 11;
                int tp   = m & (T_ - 1);
                int head = blockIdx.x;
                __half* vb = vh + ((size_t)(b * NH_ + head) * H_ + col) * T_ + tp;
                vb[0]      = __float2half(acc[mt][nt][0]);
                vb[T_]     = __float2half(acc[mt][nt][1]);
                vb[8]      = __float2half(acc[mt][nt][2]);
                vb[T_ + 8] = __float2half(acc[mt][nt][3]);
            }
        }
    }
}

// ---------------------------------------------------------------------------
// RoPE (full-D, fp16 in/out) + transpose to [B,N,T,H]. 2 elems/thread.
// rot(z)[d] = d < D/2 ? -z[2d+1] : z[2(d-D/2)]
// ---------------------------------------------------------------------------
__global__ __launch_bounds__(256)
void rope_kernel(const __half* __restrict__ q, const __half* __restrict__ k,
                 const float* __restrict__ cosb, const float* __restrict__ sinb,
                 __half* __restrict__ qo, __half* __restrict__ ko)
{
    int i = blockIdx.x * 256 + threadIdx.x;          // 0 .. M*D/2-1
    int dp   = (i & 511) * 2;                        // even d
    int row  = i >> 9;
    int tpos = row & (T_ - 1);
    int b    = row >> 11;

    float2 c2 = *(const float2*)(cosb + (size_t)tpos * D_ + dp);
    float2 s2 = *(const float2*)(sinb + (size_t)tpos * D_ + dp);
    size_t base = (size_t)row * D_;

    __half2 qv = *(const __half2*)(q + base + dp);
    __half2 kv = *(const __half2*)(k + base + dp);
    float q0 = __half2float(qv.x), q1 = __half2float(qv.y);
    float k0 = __half2float(kv.x), k1 = __half2float(kv.y);

    float qr0, qr1, kr0, kr1;
    if (dp < D_/2) {
        // partners: -q[2dp+1], -q[2dp+3]
        const __half2* qp = (const __half2*)(q + base + 2 * dp);
        const __half2* kp = (const __half2*)(k + base + 2 * dp);
        __half2 a = qp[0], bq = qp[1];
        __half2 c = kp[0], dk = kp[1];
        qr0 = -__half2float(a.y);  qr1 = -__half2float(bq.y);
        kr0 = -__half2float(c.y);  kr1 = -__half2float(dk.y);
    } else {
        // partners: q[2j], q[2j+2]  (j = dp - D/2)  -- stride-2 gather, .x of each pair
        int j = dp - D_/2;
        const __half2* qp = (const __half2*)(q + base + 2 * j);
        const __half2* kp = (const __half2*)(k + base + 2 * j);
        __half2 a = qp[0], bq = qp[1];
        __half2 c = kp[0], dk = kp[1];
        qr0 = __half2float(a.x);   qr1 = __half2float(bq.x);
        kr0 = __half2float(c.x);   kr1 = __half2float(dk.x);
    }

    int head = dp >> 7;
    int h    = dp & (H_ - 1);
    size_t oidx = ((((size_t)b*NH_ + head)*T_) + tpos)*H_ + h;
    *(__half2*)(qo + oidx) = __floats2half2_rn(q0 * c2.x + qr0 * s2.x,
                                               q1 * c2.y + qr1 * s2.y);
    *(__half2*)(ko + oidx) = __floats2half2_rn(k0 * c2.x + kr0 * s2.x,
                                               k1 * c2.y + kr1 * s2.y);
}

// ---------------------------------------------------------------------------
// fp16 tensor-core causal flash attention. Br=128, Bc=64, 8 warps x 16 rows.
// 3-stage K/V cp.async pipeline, one barrier per k-tile. exp2-domain softmax.
// smem: Qs [128][136]h | 3 x (Ks [64][136]h + Vs [128][72]h)
// ---------------------------------------------------------------------------
#define QS_BYTES    34816
#define STG_BYTES   35840            // K 17408 + V 18432
#define KS_OFF(s)   (QS_BYTES + (s)*STG_BYTES)
#define VS_OFF(s)   (KS_OFF(s) + 17408)
#define ATTN_SMEM   (QS_BYTES + 3*STG_BYTES)   // 142336

__global__ __launch_bounds__(256, 1)
void attn_kernel(const __half* __restrict__ Q, const __half* __restrict__ K,
                 const __half* __restrict__ V, float* __restrict__ out)
{
    extern __shared__ char smem[];
    const uint32_t sb = smem_u32(smem);
    const int t   = threadIdx.x;
    const int w   = t >> 5;
    const int lid = t & 31;
    const int lr  = lid >> 2;
    const int lc  = lid & 3;
    const int l7  = lid & 7;
    const int lm1 = (lid >> 3) & 1;
    const int lm2 = lid >> 4;
    const int qi  = (gridDim.x - 1) - blockIdx.x;
    const int bn  = blockIdx.y;
    const int q0  = qi * 128;
    const float sc2 = 0.08838834764831845f * 1.4426950408889634f;  // scale*log2e

    const __half* Qg = Q + ((size_t)bn * T_ + q0) * H_;
    const __half* Kg = K + (size_t)bn * T_ * H_;
    const __half* Vg = V + (size_t)bn * H_ * T_;

    auto load_kv = [&](int kt, int stg) {
        const int k0 = kt * 64;
#pragma unroll
        for (int i = 0; i < 4; i++) {
            int id  = t + i * 256;
            int row = id >> 4;
            int c   = id & 15;
            cp16(sb + KS_OFF(stg) + row * 272 + c * 16,
                 Kg + (size_t)(k0 + row) * H_ + c * 8);
        }
#pragma unroll
        for (int i = 0; i < 4; i++) {
            int id  = t + i * 256;
            int row = id >> 3;
            int c   = id & 7;
            cp16(sb + VS_OFF(stg) + row * 144 + c * 16,
                 Vg + (size_t)row * T_ + k0 + c * 8);
        }
        cp_commit();
    };

    // group0: Q + KV0 ; group1: KV1
#pragma unroll
    for (int i = 0; i < 8; i++) {
        int id  = t + i * 256;
        int row = id >> 4;
        int c   = id & 15;
        cp16(sb + row * 272 + c * 16, Qg + row * H_ + c * 8);
    }
    const int nkt = 2 * qi + 2;
    load_kv(0, 0);     // commits Q + KV0 together as group 0
    load_kv(1, 1);

    float o[16][4];
#pragma unroll
    for (int i = 0; i < 16; i++)
#pragma unroll
        for (int e = 0; e < 4; e++) o[i][e] = 0.f;
    float mi0 = -1e30f, mi1 = -1e30f, li0 = 0.f, li1 = 0.f;

#pragma unroll 1
    for (int kt = 0; kt < nkt; kt++) {
        if (kt == nkt - 1) cp_wait0(); else cp_wait1();
        __syncthreads();
        if (kt + 2 < nkt) load_kv(kt + 2, (kt + 2) % 3);

        const int k0 = kt * 64;
        if (k0 <= q0 + w * 16 + 15) {
            const int stg = kt % 3;
            const uint32_t Qs  = sb;
            const uint32_t Ksb = sb + KS_OFF(stg);
            const uint32_t Vsb = sb + VS_OFF(stg);

            // ---- S = Q K^T ----
            float s[8][4];
#pragma unroll
            for (int nt = 0; nt < 8; nt++)
#pragma unroll
                for (int e = 0; e < 4; e++) s[nt][e] = 0.f;

#pragma unroll
            for (int ks = 0; ks < 8; ks++) {
                uint32_t a[4];
                {
                    int row = w * 16 + l7 + lm1 * 8;
                    int kh  = ks * 16 + lm2 * 8;
                    ldm_x4(a, Qs + row * 272 + kh * 2);
                }
#pragma unroll
                for (int ntp = 0; ntp < 4; ntp++) {
                    uint32_t b[4];
                    int nr = ntp * 16 + l7 + lm2 * 8;
                    int kh = ks * 16 + lm1 * 8;
                    ldm_x4(b, Ksb + nr * 272 + kh * 2);
                    mma_f16(s[2*ntp],   a, b);
                    mma_f16(s[2*ntp+1], a, b + 2);
                }
            }

#pragma unroll
            for (int nt = 0; nt < 8; nt++)
#pragma unroll
                for (int e = 0; e < 4; e++) s[nt][e] *= sc2;   // log2 domain

            // ---- causal mask ----
            if (k0 + 63 > q0 + w * 16) {
                const int row0g = q0 + w * 16 + lr;
#pragma unroll
                for (int nt = 0; nt < 8; nt++) {
                    int c0 = k0 + nt * 8 + 2 * lc;
                    if (c0     > row0g)     s[nt][0] = -1e30f;
                    if (c0 + 1 > row0g)     s[nt][1] = -1e30f;
                    if (c0     > row0g + 8) s[nt][2] = -1e30f;
                    if (c0 + 1 > row0g + 8) s[nt][3] = -1e30f;
                }
            }

            // ---- online softmax (base-2) ----
            float rm0 = -1e30f, rm1 = -1e30f;
#pragma unroll
            for (int nt = 0; nt < 8; nt++) {
                rm0 = fmaxf(rm0, fmaxf(s[nt][0], s[nt][1]));
                rm1 = fmaxf(rm1, fmaxf(s[nt][2], s[nt][3]));
            }
            rm0 = fmaxf(rm0, __shfl_xor_sync(0xffffffffu, rm0, 1));
            rm0 = fmaxf(rm0, __shfl_xor_sync(0xffffffffu, rm0, 2));
            rm1 = fmaxf(rm1, __shfl_xor_sync(0xffffffffu, rm1, 1));
            rm1 = fmaxf(rm1, __shfl_xor_sync(0xffffffffu, rm1, 2));

            float mn0 = fmaxf(mi0, rm0), mn1 = fmaxf(mi1, rm1);
            float al0 = ex2(mi0 - mn0), al1 = ex2(mi1 - mn1);
            float ls0 = 0.f, ls1 = 0.f;
#pragma unroll
            for (int nt = 0; nt < 8; nt++) {
                s[nt][0] = ex2(s[nt][0] - mn0);
                s[nt][1] = ex2(s[nt][1] - mn0);
                s[nt][2] = ex2(s[nt][2] - mn1);
                s[nt][3] = ex2(s[nt][3] - mn1);
                ls0 += s[nt][0] + s[nt][1];
                ls1 += s[nt][2] + s[nt][3];
            }
            ls0 += __shfl_xor_sync(0xffffffffu, ls0, 1);
            ls0 += __shfl_xor_sync(0xffffffffu, ls0, 2);
            ls1 += __shfl_xor_sync(0xffffffffu, ls1, 1);
            ls1 += __shfl_xor_sync(0xffffffffu, ls1, 2);
            li0 = li0 * al0 + ls0;  mi0 = mn0;
            li1 = li1 * al1 + ls1;  mi1 = mn1;
#pragma unroll
            for (int i = 0; i < 16; i++) {
                o[i][0] *= al0; o[i][1] *= al0;
                o[i][2] *= al1; o[i][3] *= al1;
            }

            // ---- O += P V ----
#pragma unroll
            for (int kc = 0; kc < 4; kc++) {
                uint32_t pa[4];
                pa[0] = pack_h2(s[2*kc][0],   s[2*kc][1]);
                pa[1] = pack_h2(s[2*kc][2],   s[2*kc][3]);
                pa[2] = pack_h2(s[2*kc+1][0], s[2*kc+1][1]);
                pa[3] = pack_h2(s[2*kc+1][2], s[2*kc+1][3]);
#pragma unroll
                for (int ntp = 0; ntp < 8; ntp++) {
                    uint32_t b[4];
                    int hr = ntp * 16 + l7 + lm2 * 8;
                    int th = kc * 16 + lm1 * 8;
                    ldm_x4(b, Vsb + hr * 144 + th * 2);
                    mma_f16(o[2*ntp],   pa, b);
                    mma_f16(o[2*ntp+1], pa, b + 2);
                }
            }
        }
    }

    // ---- epilogue ----
    const float inv0 = 1.f / li0, inv1 = 1.f / li1;
    const int b    = bn >> 3;
    const int head = bn & 7;
    const int trow = q0 + w * 16 + lr;
    float* base0 = out + ((size_t)b * T_ + trow) * D_ + head * H_ + 2 * lc;
    float* base1 = base0 + 8 * (size_t)D_;
#pragma unroll
    for (int nt2 = 0; nt2 < 16; nt2++) {
        *(float2*)(base0 + nt2 * 8) = make_float2(o[nt2][0] * inv0, o[nt2][1] * inv0);
        *(float2*)(base1 + nt2 * 8) = make_float2(o[nt2][2] * inv1, o[nt2][3] * inv1);
    }
}

// ---------------------------------------------------------------------------
extern "C" void kernel_launch(void* const* d_in, const int* in_sizes, int n_in,
                              void* d_out, int out_size)
{
    const float* x    = (const float*)d_in[0];
    const float* wq   = (const float*)d_in[1];
    const float* wk   = (const float*)d_in[2];
    const float* wv   = (const float*)d_in[3];
    const float* cosb = (const float*)d_in[4];
    const float* sinb = (const float*)d_in[5];
    float* out = (float*)d_out;

    __half *qth, *kth, *qh, *kh, *vh, *xh, *wh;
    cudaGetSymbolAddress((void**)&qth, g_qth);
    cudaGetSymbolAddress((void**)&kth, g_kth);
    cudaGetSymbolAddress((void**)&qh,  g_qh);
    cudaGetSymbolAddress((void**)&kh,  g_kh);
    cudaGetSymbolAddress((void**)&vh,  g_vh);
    cudaGetSymbolAddress((void**)&xh,  g_xh);
    cudaGetSymbolAddress((void**)&wh,  g_wh);

    const int n4x = (M_ * D_) / 4;           // 2097152
    const int n4w = (D_ * D_) / 4;           // 262144
    const int ntot = n4x + 3 * n4w;          // multiple of 256
    prep_h<<<ntot / 256, 256>>>((const float4*)x, (const float4*)wq,
                                (const float4*)wk, (const float4*)wv,
                                (uint2*)xh, (uint2*)wh, n4x, n4w);

    cudaFuncSetAttribute((const void*)gemm_mma_kernel,
                         cudaFuncAttributeMaxDynamicSharedMemorySize, GSMEM);
    gemm_mma_kernel<<<dim3(D_/128, M_/128, 3), 256, GSMEM>>>(xh, wh, qth, kth, vh);

    rope_kernel<<<(M_*D_/2) / 256, 256>>>(qth, kth, cosb, sinb, qh, kh);

    cudaFuncSetAttribute((const void*)attn_kernel,
                         cudaFuncAttributeMaxDynamicSharedMemorySize, ATTN_SMEM);
    attn_kernel<<<dim3(T_/128, B_*NH_), 256, ATTN_SMEM>>>(qh, kh, vh, out);
}